// round 15
// baseline (speedup 1.0000x reference)
#include <cuda_runtime.h>
#include <cuda_bf16.h>
#include <math.h>
#include <stdint.h>

#define BB  8
#define CC  256
#define MIDD 32
#define NN  4096
#define MSHIFT  40.0f
#define MSHIFT2 34.4548225f   // MSHIFT - ln(256): folds x256 scale into exp

// ---------------- scratch ----------------------------------------------------
__device__ __nv_bfloat16 g_Ah[BB][NN*MIDD];       // A bf16, [i][m]
__device__ __nv_bfloat16 g_Bh[BB][NN*MIDD];       // B bf16, [j][m]
__device__ float g_iZ [BB*NN];                    // 1/Z[j]
__device__ uint8_t g_Cs8[BB][CC*NN];              // (WcX+bc) e4m3 [k][j]
__device__ float g_O  [BB][NN*CC];                // out [i][k] (== Y[c][n] flat)

__device__ __forceinline__ uint32_t smem_u32(const void* p) {
    uint32_t a;
    asm("{ .reg .u64 t; cvta.to.shared.u64 t, %1; cvt.u32.u64 %0, t; }" : "=r"(a) : "l"(p));
    return a;
}
__device__ __forceinline__ uint32_t pk_bf2(float a, float b) {
    __nv_bfloat162 h = __floats2bfloat162_rn(a, b);
    return *(uint32_t*)&h;
}
__device__ __forceinline__ uint16_t pk_e4(float lo, float hi) {
    uint16_t r;
    asm("cvt.rn.satfinite.e4m3x2.f32 %0, %1, %2;" : "=h"(r) : "f"(hi), "f"(lo));
    return r;   // lo -> byte0, hi -> byte1
}
__device__ __forceinline__ float to_tf32f(float f) {
    uint32_t u;
    asm("cvt.rna.tf32.f32 %0, %1;" : "=r"(u) : "f"(f));
    return __uint_as_float(u);
}
#define CP16(dst, src) asm volatile("cp.async.cg.shared.global [%0], [%1], 16;" :: "r"(dst), "l"(src))
#define CP_COMMIT()    asm volatile("cp.async.commit_group;" ::: "memory")
#define CP_WAIT(n)     asm volatile("cp.async.wait_group %0;" :: "n"(n) : "memory")

__device__ __forceinline__ void mma_bf16(float* c, const uint32_t* a, const uint32_t* b) {
    asm volatile(
        "mma.sync.aligned.m16n8k16.row.col.f32.bf16.bf16.f32 "
        "{%0,%1,%2,%3}, {%4,%5,%6,%7}, {%8,%9}, {%0,%1,%2,%3};"
        : "+f"(c[0]), "+f"(c[1]), "+f"(c[2]), "+f"(c[3])
        : "r"(a[0]), "r"(a[1]), "r"(a[2]), "r"(a[3]), "r"(b[0]), "r"(b[1]));
}
__device__ __forceinline__ void mma_fp8(float* c, const uint32_t* a, const uint32_t* b) {
    asm volatile(
        "mma.sync.aligned.m16n8k32.row.col.f32.e4m3.e4m3.f32 "
        "{%0,%1,%2,%3}, {%4,%5,%6,%7}, {%8,%9}, {%0,%1,%2,%3};"
        : "+f"(c[0]), "+f"(c[1]), "+f"(c[2]), "+f"(c[3])
        : "r"(a[0]), "r"(a[1]), "r"(a[2]), "r"(a[3]), "r"(b[0]), "r"(b[1]));
}
__device__ __forceinline__ void mma_tf32(float* c, const uint32_t* a, const uint32_t* b) {
    asm volatile(
        "mma.sync.aligned.m16n8k8.row.col.f32.tf32.tf32.f32 "
        "{%0,%1,%2,%3}, {%4,%5,%6,%7}, {%8,%9}, {%0,%1,%2,%3};"
        : "+f"(c[0]), "+f"(c[1]), "+f"(c[2]), "+f"(c[3])
        : "r"(a[0]), "r"(a[1]), "r"(a[2]), "r"(a[3]), "r"(b[0]), "r"(b[1]));
}
__device__ __forceinline__ void ldsm_x4(uint32_t& r0, uint32_t& r1, uint32_t& r2, uint32_t& r3,
                                        uint32_t addr) {
    asm volatile("ldmatrix.sync.aligned.m8n8.x4.shared.b16 {%0,%1,%2,%3}, [%4];"
        : "=r"(r0), "=r"(r1), "=r"(r2), "=r"(r3) : "r"(addr));
}
__device__ __forceinline__ void ldsm_x2(uint32_t& r0, uint32_t& r1, uint32_t addr) {
    asm volatile("ldmatrix.sync.aligned.m8n8.x2.shared.b16 {%0,%1}, [%2];"
        : "=r"(r0), "=r"(r1) : "r"(addr));
}

// ---------------- K1: A,B projections -> bf16 [row][m] --------------------------
__global__ void k_ab(const float* __restrict__ x,
                     const float* __restrict__ wa, const float* __restrict__ ba,
                     const float* __restrict__ wb, const float* __restrict__ bb)
{
    __shared__ float ws[MIDD*CC];
    __shared__ float bs[MIDD];
    const int b = blockIdx.y;
    const int which = blockIdx.z;
    const float* w    = which ? wb : wa;
    const float* bias = which ? bb : ba;
    __nv_bfloat16* oh = which ? g_Bh[b] : g_Ah[b];

    for (int i = threadIdx.x; i < MIDD*CC; i += 256) ws[i] = w[i];
    if (threadIdx.x < MIDD) bs[threadIdx.x] = bias[threadIdx.x];
    __syncthreads();

    const int n = blockIdx.x*256 + threadIdx.x;
    const float* xb = x + (size_t)b*CC*NN;
    float acc[MIDD];
    #pragma unroll
    for (int m = 0; m < MIDD; m++) acc[m] = bs[m];
    for (int c = 0; c < CC; c++) {
        float xv = xb[c*NN + n];
        #pragma unroll
        for (int m = 0; m < MIDD; m++) acc[m] += ws[m*CC + c] * xv;
    }
    uint32_t pk[16];
    #pragma unroll
    for (int q = 0; q < 16; q++) pk[q] = pk_bf2(acc[2*q], acc[2*q+1]);
    uint4* dst = (uint4*)(oh + (size_t)n*MIDD);
    #pragma unroll
    for (int q = 0; q < 4; q++)
        dst[q] = make_uint4(pk[q*4], pk[q*4+1], pk[q*4+2], pk[q*4+3]);
}

// ---------------- K2: k_z — iZ[j] via bf16 logit mma ---------------------------
#define LPAD 40
#define KZ_SMEM (128*LPAD*2*3 + 512)

__global__ void __launch_bounds__(256, 2) k_z()
{
    extern __shared__ char smz[];
    __nv_bfloat16* Bs  = (__nv_bfloat16*)smz;
    __nv_bfloat16* As0 = Bs + 128*LPAD;
    float* Zsm = (float*)(smz + 128*LPAD*2*3);

    const int b  = blockIdx.y;
    const int j0 = blockIdx.x * 128;
    const __nv_bfloat16* Ah = g_Ah[b];
    const __nv_bfloat16* Bh = g_Bh[b];
    const int tid  = threadIdx.x;
    const int lane = tid & 31;
    const int warp = tid >> 5;
    const int wm   = warp & 1;
    const int wn   = warp >> 1;
    const int lr   = lane >> 2;
    const int lc   = lane & 3;

    const int a_lr = ((lane>>3)&1)*8 + (lane&7);
    const int a_cb = ((lane>>4)&1)*16;
    const int b_rw = lane&7;
    const int b_cb = ((lane>>3)&1)*16;

    #pragma unroll
    for (int r = 0; r < 2; r++) {
        int idx = tid + 256*r;
        int row = idx >> 2, q = idx & 3;
        *(uint4*)(Bs + row*LPAD + q*8) = *(const uint4*)(Bh + (size_t)(j0+row)*MIDD + q*8);
    }
    if (tid < 128) Zsm[tid] = 0.f;

    #define STAGE_AZ(dst, ib) do {                                              \
        _Pragma("unroll")                                                       \
        for (int r = 0; r < 2; r++) {                                           \
            int idx = tid + 256*r;                                              \
            int row = idx >> 2, q = idx & 3;                                    \
            *(uint4*)((dst) + row*LPAD + q*8) =                                 \
                *(const uint4*)(Ah + (size_t)((ib)+row)*MIDD + q*8);            \
        }                                                                       \
    } while (0)

    STAGE_AZ(As0, 0);
    __syncthreads();

    float z0[4], z1[4];
    #pragma unroll
    for (int nf = 0; nf < 4; nf++) { z0[nf] = 0.f; z1[nf] = 0.f; }

    for (int ic = 0; ic < 32; ic++) {
        const int s = ic & 1;
        const uint32_t asb = smem_u32(As0 + s*128*LPAD);
        const uint32_t bsb = smem_u32(Bs);
        if (ic + 1 < 32) STAGE_AZ(As0 + (s^1)*128*LPAD, (ic+1)*128);

        float acc[4][4][4];
        #pragma unroll
        for (int mf = 0; mf < 4; mf++)
            #pragma unroll
            for (int nf = 0; nf < 4; nf++)
                #pragma unroll
                for (int q = 0; q < 4; q++) acc[mf][nf][q] = 0.f;

        #pragma unroll
        for (int ks = 0; ks < 2; ks++) {
            const int jbB = ks * 32;
            uint32_t afr[4][4], bfr[4][2];
            #pragma unroll
            for (int mf = 0; mf < 4; mf++)
                ldsm_x4(afr[mf][0], afr[mf][1], afr[mf][2], afr[mf][3],
                        asb + (wm*64 + mf*16 + a_lr)*(LPAD*2) + jbB + a_cb);
            #pragma unroll
            for (int nf = 0; nf < 4; nf++)
                ldsm_x2(bfr[nf][0], bfr[nf][1],
                        bsb + (wn*32 + nf*8 + b_rw)*(LPAD*2) + jbB + b_cb);
            #pragma unroll
            for (int mf = 0; mf < 4; mf++)
                #pragma unroll
                for (int nf = 0; nf < 4; nf++)
                    mma_bf16(acc[mf][nf], afr[mf], bfr[nf]);
        }

        #pragma unroll
        for (int mf = 0; mf < 4; mf++)
            #pragma unroll
            for (int nf = 0; nf < 4; nf++) {
                z0[nf] += __expf(acc[mf][nf][0] - MSHIFT) + __expf(acc[mf][nf][2] - MSHIFT);
                z1[nf] += __expf(acc[mf][nf][1] - MSHIFT) + __expf(acc[mf][nf][3] - MSHIFT);
            }
        __syncthreads();
    }

    #pragma unroll
    for (int nf = 0; nf < 4; nf++) {
        float s0 = z0[nf], s1 = z1[nf];
        #pragma unroll
        for (int msk = 4; msk <= 16; msk <<= 1) {
            s0 += __shfl_xor_sync(0xFFFFFFFF, s0, msk);
            s1 += __shfl_xor_sync(0xFFFFFFFF, s1, msk);
        }
        if (lr == 0) {
            atomicAdd(&Zsm[wn*32 + nf*8 + 2*lc],     s0);
            atomicAdd(&Zsm[wn*32 + nf*8 + 2*lc + 1], s1);
        }
    }
    __syncthreads();
    if (tid < 128) g_iZ[b*NN + j0 + tid] = 1.f / Zsm[tid];
}

// ---------------- K3: bf16 mma conv -> e4m3: Cs8[k][n] = Wc X + bc --------------
#define KCPAD 40
__global__ void __launch_bounds__(256, 2) k_c_mma(
    const float* __restrict__ x, const float* __restrict__ wc,
    const float* __restrict__ bc)
{
    __shared__ __nv_bfloat16 Wt[2][128*KCPAD];
    __shared__ __nv_bfloat16 Xt[2][128*KCPAD];

    const int tid  = threadIdx.x;
    const int lane = tid & 31;
    const int warp = tid >> 5;
    const int wm   = warp & 1;
    const int wn   = warp >> 1;
    const int lr   = lane >> 2;
    const int lc   = lane & 3;
    const int n0   = blockIdx.x * 128;
    const int b    = blockIdx.y;
    const int kz   = blockIdx.z;
    const float* xb = x + (size_t)b*CC*NN;

    const int a_lr = ((lane>>3)&1)*8 + (lane&7);
    const int a_cb = ((lane>>4)&1)*16;
    const int b_rw = lane&7;
    const int b_cb = ((lane>>3)&1)*16;

    float acc[4][4][4];
    #pragma unroll
    for (int mf = 0; mf < 4; mf++)
        #pragma unroll
        for (int nf = 0; nf < 4; nf++)
            #pragma unroll
            for (int q = 0; q < 4; q++) acc[mf][nf][q] = 0.f;

    const int xt = tid & 127, xch = tid >> 7;

    #define STAGE_C(s, c0) do {                                                 \
        _Pragma("unroll")                                                       \
        for (int r = 0; r < 8; r++) {                                           \
            int idx = tid + 256*r;                                              \
            int k = idx >> 4, cp = idx & 15;                                    \
            float2 w2 = *(const float2*)(wc + (kz*128 + k)*CC + (c0) + cp*2);   \
            *(uint32_t*)&Wt[s][k*KCPAD + cp*2] = pk_bf2(w2.x, w2.y);            \
        }                                                                       \
        _Pragma("unroll")                                                       \
        for (int r = 0; r < 16; r++) {                                          \
            int c = xch*16 + r;                                                 \
            Xt[s][xt*KCPAD + c] =                                               \
                __float2bfloat16(xb[(size_t)((c0) + c)*NN + n0 + xt]);          \
        }                                                                       \
    } while (0)

    STAGE_C(0, 0);
    __syncthreads();

    for (int ch = 0; ch < 8; ch++) {
        const int s = ch & 1;
        if (ch + 1 < 8) STAGE_C(s^1, (ch+1)*32);

        const uint32_t wtb = smem_u32(&Wt[s][0]);
        const uint32_t xtb = smem_u32(&Xt[s][0]);
        #pragma unroll
        for (int ks = 0; ks < 2; ks++) {
            const int jbB = ks * 32;
            uint32_t afr[4][4], bfr[4][2];
            #pragma unroll
            for (int mf = 0; mf < 4; mf++)
                ldsm_x4(afr[mf][0], afr[mf][1], afr[mf][2], afr[mf][3],
                        wtb + (wm*64 + mf*16 + a_lr)*(KCPAD*2) + jbB + a_cb);
            #pragma unroll
            for (int nf = 0; nf < 4; nf++)
                ldsm_x2(bfr[nf][0], bfr[nf][1],
                        xtb + (wn*32 + nf*8 + b_rw)*(KCPAD*2) + jbB + b_cb);
            #pragma unroll
            for (int mf = 0; mf < 4; mf++)
                #pragma unroll
                for (int nf = 0; nf < 4; nf++)
                    mma_bf16(acc[mf][nf], afr[mf], bfr[nf]);
        }
        __syncthreads();
    }

    uint8_t* Cb = g_Cs8[b];
    #pragma unroll
    for (int mf = 0; mf < 4; mf++) {
        int krow = kz*128 + wm*64 + mf*16 + lr;
        float bc0 = __ldg(bc + krow), bc8 = __ldg(bc + krow + 8);
        #pragma unroll
        for (int nf = 0; nf < 4; nf++) {
            int col = n0 + wn*32 + nf*8 + 2*lc;
            *(uint16_t*)(Cb + (size_t)krow*NN + col) =
                pk_e4(acc[mf][nf][0] + bc0, acc[mf][nf][1] + bc0);
            *(uint16_t*)(Cb + (size_t)(krow+8)*NN + col) =
                pk_e4(acc[mf][nf][2] + bc8, acc[mf][nf][3] + bc8);
        }
    }
}

// ---------------- K4: fused attention-out; fp8 main GEMM; M=64 ------------------
// smem: AsH bf16[64*40] | Et fp8 2x[64*80B] | Cs fp8 2x[256*80B] | iZ 2x256B
#define EROW8 80
#define OF_ET 5120
#define ETB   5120
#define OF_CS 15360
#define CSB   20480
#define OF_IZ 56320
#define KOF_SMEM 56832

__global__ void __launch_bounds__(256, 2) k_out_f()
{
    extern __shared__ char sm[];
    const uint32_t sb = smem_u32(sm);
    const int tid  = threadIdx.x;
    const int lane = tid & 31;
    const int warp = tid >> 5;
    const int wn   = warp;        // main: N eighth
    const int wi   = warp & 1;    // logit: i half
    const int wj   = warp >> 1;   // logit: j quarter
    const int lr   = lane >> 2;
    const int lc   = lane & 3;
    const int b    = blockIdx.y;
    const int i0   = blockIdx.x * 64;

    const __nv_bfloat16* Ah = g_Ah[b];
    const __nv_bfloat16* Bh = g_Bh[b];
    const uint8_t* Ch = g_Cs8[b];
    const float* iZb = g_iZ + b*NN;

    const int a_lr = ((lane>>3)&1)*8 + (lane&7);
    const int a_cb = ((lane>>4)&1)*16;
    const int b_rw = lane&7;
    const int b_cb = ((lane>>3)&1)*16;

    #define ISSUE_CS(ch, s) do {                                                \
        uint32_t cb = sb + OF_CS + (s)*CSB;                                     \
        int _j = (ch)*64;                                                       \
        _Pragma("unroll")                                                       \
        for (int r = 0; r < 4; r++) {                                           \
            int id = tid + 256*r; int row = id >> 2, q = id & 3;                \
            CP16(cb + row*EROW8 + q*16,                                         \
                 (const char*)(Ch + (size_t)row*NN + _j) + q*16);               \
        }                                                                       \
        if (tid < 16)                                                           \
            CP16(sb + OF_IZ + (s)*256 + tid*16,                                 \
                 (const char*)(iZb + _j) + tid*16);                             \
        CP_COMMIT();                                                            \
    } while (0)

    // logit tile 64i x 64j: bf16 mma; A from smem (ldsm), B direct from gmem
    #define LOGIT_MMA(lacc, ch) do {                                            \
        const int _j = (ch)*64;                                                 \
        uint32_t breg[2][2][2];                                                 \
        _Pragma("unroll")                                                       \
        for (int ks = 0; ks < 2; ks++)                                          \
            _Pragma("unroll")                                                   \
            for (int nf = 0; nf < 2; nf++) {                                    \
                int jcol = _j + wj*16 + nf*8 + lr;                              \
                breg[ks][nf][0] = *(const uint32_t*)(Bh + (size_t)jcol*MIDD + ks*16 + 2*lc);     \
                breg[ks][nf][1] = *(const uint32_t*)(Bh + (size_t)jcol*MIDD + ks*16 + 2*lc + 8); \
            }                                                                   \
        _Pragma("unroll")                                                       \
        for (int mf = 0; mf < 2; mf++)                                          \
            _Pragma("unroll")                                                   \
            for (int nf = 0; nf < 2; nf++)                                      \
                _Pragma("unroll")                                               \
                for (int q = 0; q < 4; q++) lacc[mf][nf][q] = 0.f;              \
        _Pragma("unroll")                                                       \
        for (int ks = 0; ks < 2; ks++) {                                        \
            uint32_t afr[2][4];                                                 \
            _Pragma("unroll")                                                   \
            for (int mf = 0; mf < 2; mf++)                                      \
                ldsm_x4(afr[mf][0], afr[mf][1], afr[mf][2], afr[mf][3],         \
                        sb + (wi*32 + mf*16 + a_lr)*(LPAD*2) + ks*32 + a_cb);   \
            _Pragma("unroll")                                                   \
            for (int mf = 0; mf < 2; mf++)                                      \
                _Pragma("unroll")                                               \
                for (int nf = 0; nf < 2; nf++)                                  \
                    mma_bf16(lacc[mf][nf], afr[mf], breg[ks][nf]);              \
        }                                                                       \
    } while (0)

    // exp with x256 scale (via MSHIFT2), x iZ, pack e4m3
    #define EXP_STORE(lacc, s) do {                                             \
        uint8_t* Et = (uint8_t*)(sm + OF_ET + (s)*ETB);                         \
        const float* izp = (const float*)(sm + OF_IZ + (s)*256);                \
        _Pragma("unroll")                                                       \
        for (int nf = 0; nf < 2; nf++) {                                        \
            const int col0 = wj*16 + nf*8 + 2*lc;                               \
            const float iz0 = izp[col0], iz1 = izp[col0 + 1];                   \
            _Pragma("unroll")                                                   \
            for (int mf = 0; mf < 2; mf++) {                                    \
                const int row = wi*32 + mf*16 + lr;                             \
                float e0 = __expf(lacc[mf][nf][0] - MSHIFT2) * iz0;             \
                float e1 = __expf(lacc[mf][nf][1] - MSHIFT2) * iz1;             \
                float e2 = __expf(lacc[mf][nf][2] - MSHIFT2) * iz0;             \
                float e3 = __expf(lacc[mf][nf][3] - MSHIFT2) * iz1;             \
                *(uint16_t*)(Et + row*EROW8 + col0)     = pk_e4(e0, e1);        \
                *(uint16_t*)(Et + (row+8)*EROW8 + col0) = pk_e4(e2, e3);        \
            }                                                                   \
        }                                                                       \
    } while (0)

    // ---- prologue: stage AsH [64 i][32 m] bf16 (pure copy) ----
    {
        __nv_bfloat16* AsH = (__nv_bfloat16*)sm;
        int row = tid >> 2, q = tid & 3;
        *(uint4*)(AsH + row*LPAD + q*8) = *(const uint4*)(Ah + (size_t)(i0+row)*MIDD + q*8);
    }
    ISSUE_CS(0, 0);
    CP_WAIT(0);
    __syncthreads();

    {
        float lacc[2][2][4];
        LOGIT_MMA(lacc, 0);
        EXP_STORE(lacc, 0);
    }
    __syncthreads();
    ISSUE_CS(1, 1);

    float acc[4][4][4];
    #pragma unroll
    for (int mf = 0; mf < 4; mf++)
        #pragma unroll
        for (int nf = 0; nf < 4; nf++)
            #pragma unroll
            for (int q = 0; q < 4; q++) acc[mf][nf][q] = 0.f;

    // ---- main loop: fp8 mma, 2 k-steps of 32 ----
    for (int ch = 0; ch < 64; ch++) {
        const int s = ch & 1;

        const uint32_t etb = sb + OF_ET + s*ETB;
        const uint32_t csb = sb + OF_CS + s*CSB;
        #pragma unroll
        for (int ks = 0; ks < 2; ks++) {
            const int jbB = ks * 32;
            uint32_t afr[4][4], bfr[4][2];
            #pragma unroll
            for (int mf = 0; mf < 4; mf++)
                ldsm_x4(afr[mf][0], afr[mf][1], afr[mf][2], afr[mf][3],
                        etb + (mf*16 + a_lr)*EROW8 + jbB + a_cb);
            #pragma unroll
            for (int nf = 0; nf < 4; nf++)
                ldsm_x2(bfr[nf][0], bfr[nf][1],
                        csb + (wn*32 + nf*8 + b_rw)*EROW8 + jbB + b_cb);
            #pragma unroll
            for (int mf = 0; mf < 4; mf++)
                #pragma unroll
                for (int nf = 0; nf < 4; nf++)
                    mma_fp8(acc[mf][nf], afr[mf], bfr[nf]);
        }

        if (ch + 1 < 64) {
            float lacc[2][2][4];
            LOGIT_MMA(lacc, ch+1);
            CP_WAIT(0);
            EXP_STORE(lacc, s^1);
            __syncthreads();
            if (ch + 2 < 64) ISSUE_CS(ch+2, s);
        }
    }

    // epilogue: undo x256 scale
    const float SC = 1.0f / 256.0f;
    float* Ob = g_O[b];
    #pragma unroll
    for (int mf = 0; mf < 4; mf++) {
        int row0 = i0 + mf*16 + lr;
        #pragma unroll
        for (int nf = 0; nf < 4; nf++) {
            int col = wn*32 + nf*8 + 2*lc;
            *(float2*)(Ob + (size_t)row0*CC + col) =
                make_float2(acc[mf][nf][0]*SC, acc[mf][nf][1]*SC);
            *(float2*)(Ob + (size_t)(row0+8)*CC + col) =
                make_float2(acc[mf][nf][2]*SC, acc[mf][nf][3]*SC);
        }
    }
}

// ---------------- K5: tf32 mma conv, frag-order: out = Wo(beta*Y + X) + bo ------
#define APAD 36
#define KF_SMEM (16384*4)
__global__ void __launch_bounds__(256, 2) k_final_mma(
    const float* __restrict__ x, const float* __restrict__ wo,
    const float* __restrict__ bo, const float* __restrict__ beta,
    float* __restrict__ out)
{
    extern __shared__ float smf[];
    float* WtF0 = smf;
    float* VtF0 = smf + 8192;

    const int tid  = threadIdx.x;
    const int lane = tid & 31;
    const int warp = tid >> 5;
    const int wm   = warp & 1;
    const int wn   = warp >> 1;
    const int lr   = lane >> 2;
    const int lc   = lane & 3;
    const int n0   = blockIdx.x * 128;
    const int b    = blockIdx.y;
    const int kz   = blockIdx.z;
    const float bt = beta[0];
    const float* xb = x + (size_t)b*CC*NN;
    const float* Yb = g_O[b];

    float acc[4][4][4];
    #pragma unroll
    for (int mf = 0; mf < 4; mf++)
        #pragma unroll
        for (int nf = 0; nf < 4; nf++)
            #pragma unroll
            for (int q = 0; q < 4; q++) acc[mf][nf][q] = 0.f;

    const int xt = tid & 127, xch = tid >> 7;

    #define STAGE_F(s, c0) do {                                                 \
        float* WtF = WtF0 + (s)*4096;                                           \
        float* VtF = VtF0 + (s)*4096;                                           \
        _Pragma("unroll")                                                       \
        for (int r = 0; r < 16; r++) {                                          \
            int idx = tid + 256*r;                                              \
            int k = idx >> 5, c = idx & 31;                                     \
            int t = k >> 4, hi = (k >> 3) & 1, lr8 = k & 7;                     \
            int ks = c >> 3, c8 = c & 7, lcb = c8 & 3, q = hi + ((c8>>2) << 1); \
            WtF[((t*4 + ks)*32 + lr8*4 + lcb)*4 + q] =                          \
                to_tf32f(wo[(kz*128 + k)*CC + (c0) + c]);                       \
        }                                                                       \
        _Pragma("unroll")                                                       \
        for (int r = 0; r < 16; r++) {                                          \
            int c = xch*16 + r;                                                 \
            size_t off = (size_t)((c0) + c)*NN + n0 + xt;                       \
            int jt = xt >> 3, lr8 = xt & 7;                                     \
            int ks = c >> 3, lcb = c & 3, qb = (c >> 2) & 1;                    \
            VtF[((jt*4 + ks)*32 + lr8*4 + lcb)*2 + qb] =                        \
                to_tf32f(fmaf(bt, Yb[off], xb[off]));                           \
        }                                                                       \
    } while (0)

    STAGE_F(0, 0);
    __syncthreads();

    for (int ch = 0; ch < 8; ch++) {
        const int s = ch & 1;
        if (ch + 1 < 8) STAGE_F(s^1, (ch+1)*32);

        const float4* WtF = (const float4*)(WtF0 + s*4096);
        const float2* VtF = (const float2*)(VtF0 + s*4096);
        #pragma unroll
        for (int ks = 0; ks < 4; ks++) {
            uint32_t afr[4][4], bfr[4][2];
            #pragma unroll
            for (int mf = 0; mf < 4; mf++) {
                float4 av = WtF[((wm*4 + mf)*4 + ks)*32 + lane];
                afr[mf][0] = __float_as_uint(av.x); afr[mf][1] = __float_as_uint(av.y);
                afr[mf][2] = __float_as_uint(av.z); afr[mf][3] = __float_as_uint(av.w);
            }
            #pragma unroll
            for (int nf = 0; nf < 4; nf++) {
                float2 bv = VtF[((wn*4 + nf)*4 + ks)*32 + lane];
                bfr[nf][0] = __float_as_uint(bv.x); bfr[nf][1] = __float_as_uint(bv.y);
            }
            #pragma unroll
            for (int mf = 0; mf < 4; mf++)
                #pragma unroll
                for (int nf = 0; nf < 4; nf++)
                    mma_tf32(acc[mf][nf], afr[mf], bfr[nf]);
        }
        __syncthreads();
    }

    #pragma unroll
    for (int mf = 0; mf < 4; mf++) {
        int krow = kz*128 + wm*64 + mf*16 + lr;
        float b0 = __ldg(bo + krow), b8 = __ldg(bo + krow + 8);
        #pragma unroll
        for (int nf = 0; nf < 4; nf++) {
            int col = n0 + wn*32 + nf*8 + 2*lc;
            *(float2*)(out + ((size_t)b*CC + krow)*NN + col) =
                make_float2(acc[mf][nf][0] + b0, acc[mf][nf][1] + b0);
            *(float2*)(out + ((size_t)b*CC + krow + 8)*NN + col) =
                make_float2(acc[mf][nf][2] + b8, acc[mf][nf][3] + b8);
        }
    }
}

// ---------------- launch --------------------------------------------------------
extern "C" void kernel_launch(void* const* d_in, const int* in_sizes, int n_in,
                              void* d_out, int out_size)
{
    const float* x    = (const float*)d_in[0];
    const float* wa   = (const float*)d_in[1];
    const float* ba   = (const float*)d_in[2];
    const float* wb   = (const float*)d_in[3];
    const float* bb   = (const float*)d_in[4];
    const float* wc   = (const float*)d_in[5];
    const float* bc   = (const float*)d_in[6];
    const float* wo   = (const float*)d_in[7];
    const float* bo   = (const float*)d_in[8];
    const float* beta = (const float*)d_in[9];
    float* out = (float*)d_out;

    cudaFuncSetAttribute(k_z,         cudaFuncAttributeMaxDynamicSharedMemorySize, KZ_SMEM);
    cudaFuncSetAttribute(k_out_f,     cudaFuncAttributeMaxDynamicSharedMemorySize, KOF_SMEM);
    cudaFuncSetAttribute(k_final_mma, cudaFuncAttributeMaxDynamicSharedMemorySize, KF_SMEM);

    k_ab       <<<dim3(NN/256, BB, 2),  256>>>(x, wa, ba, wb, bb);
    k_z        <<<dim3(NN/128, BB),     256, KZ_SMEM>>>();
    k_c_mma    <<<dim3(NN/128, BB, 2),  256>>>(x, wc, bc);
    k_out_f    <<<dim3(NN/64, BB),      256, KOF_SMEM>>>();
    k_final_mma<<<dim3(NN/128, BB, 2),  256, KF_SMEM>>>(x, wo, bo, beta, out);
}

// round 17
// speedup vs baseline: 1.0605x; 1.0605x over previous
#include <cuda_runtime.h>
#include <cuda_bf16.h>
#include <math.h>
#include <stdint.h>

#define BB  8
#define CC  256
#define MIDD 32
#define NN  4096
#define MSHIFT 40.0f

// ---------------- scratch ----------------------------------------------------
__device__ __nv_bfloat16 g_Ah[BB][NN*MIDD];       // A bf16, [i][m] row-major
__device__ __nv_bfloat16 g_Bh[BB][NN*MIDD];       // B bf16, [j][m] row-major
__device__ float g_iZ [BB*NN];                    // 1/Z[j]
__device__ __nv_bfloat16 g_CsH[BB][CC*NN];        // (WcX+bc)  [k][j] bf16 (raw)
__device__ float g_O  [BB][NN*CC];                // out [i][k] (== Y[c][n] flat)

__device__ __forceinline__ uint32_t smem_u32(const void* p) {
    uint32_t a;
    asm("{ .reg .u64 t; cvta.to.shared.u64 t, %1; cvt.u32.u64 %0, t; }" : "=r"(a) : "l"(p));
    return a;
}
__device__ __forceinline__ uint32_t pk_bf2(float a, float b) {
    __nv_bfloat162 h = __floats2bfloat162_rn(a, b);
    return *(uint32_t*)&h;
}
__device__ __forceinline__ float to_tf32f(float f) {
    uint32_t u;
    asm("cvt.rna.tf32.f32 %0, %1;" : "=r"(u) : "f"(f));
    return __uint_as_float(u);
}
#define CP16(dst, src) asm volatile("cp.async.cg.shared.global [%0], [%1], 16;" :: "r"(dst), "l"(src))
#define CP_COMMIT()    asm volatile("cp.async.commit_group;" ::: "memory")
#define CP_WAIT(n)     asm volatile("cp.async.wait_group %0;" :: "n"(n) : "memory")

__device__ __forceinline__ void mma_bf16(float* c, const uint32_t* a, const uint32_t* b) {
    asm volatile(
        "mma.sync.aligned.m16n8k16.row.col.f32.bf16.bf16.f32 "
        "{%0,%1,%2,%3}, {%4,%5,%6,%7}, {%8,%9}, {%0,%1,%2,%3};"
        : "+f"(c[0]), "+f"(c[1]), "+f"(c[2]), "+f"(c[3])
        : "r"(a[0]), "r"(a[1]), "r"(a[2]), "r"(a[3]), "r"(b[0]), "r"(b[1]));
}
__device__ __forceinline__ void mma_tf32(float* c, const uint32_t* a, const uint32_t* b) {
    asm volatile(
        "mma.sync.aligned.m16n8k8.row.col.f32.tf32.tf32.f32 "
        "{%0,%1,%2,%3}, {%4,%5,%6,%7}, {%8,%9}, {%0,%1,%2,%3};"
        : "+f"(c[0]), "+f"(c[1]), "+f"(c[2]), "+f"(c[3])
        : "r"(a[0]), "r"(a[1]), "r"(a[2]), "r"(a[3]), "r"(b[0]), "r"(b[1]));
}
__device__ __forceinline__ void ldsm_x4(uint32_t& r0, uint32_t& r1, uint32_t& r2, uint32_t& r3,
                                        uint32_t addr) {
    asm volatile("ldmatrix.sync.aligned.m8n8.x4.shared.b16 {%0,%1,%2,%3}, [%4];"
        : "=r"(r0), "=r"(r1), "=r"(r2), "=r"(r3) : "r"(addr));
}

// ---------------- K1: A,B projections -> bf16 [row][m] --------------------------
__global__ void k_ab(const float* __restrict__ x,
                     const float* __restrict__ wa, const float* __restrict__ ba,
                     const float* __restrict__ wb, const float* __restrict__ bb)
{
    __shared__ float ws[MIDD*CC];
    __shared__ float bs[MIDD];
    const int b = blockIdx.y;
    const int which = blockIdx.z;
    const float* w    = which ? wb : wa;
    const float* bias = which ? bb : ba;
    __nv_bfloat16* oh = which ? g_Bh[b] : g_Ah[b];

    for (int i = threadIdx.x; i < MIDD*CC; i += 256) ws[i] = w[i];
    if (threadIdx.x < MIDD) bs[threadIdx.x] = bias[threadIdx.x];
    __syncthreads();

    const int n = blockIdx.x*256 + threadIdx.x;
    const float* xb = x + (size_t)b*CC*NN;
    float acc[MIDD];
    #pragma unroll
    for (int m = 0; m < MIDD; m++) acc[m] = bs[m];
    for (int c = 0; c < CC; c++) {
        float xv = xb[c*NN + n];
        #pragma unroll
        for (int m = 0; m < MIDD; m++) acc[m] += ws[m*CC + c] * xv;
    }
    uint32_t pk[16];
    #pragma unroll
    for (int q = 0; q < 16; q++) pk[q] = pk_bf2(acc[2*q], acc[2*q+1]);
    uint4* dst = (uint4*)(oh + (size_t)n*MIDD);
    #pragma unroll
    for (int q = 0; q < 4; q++)
        dst[q] = make_uint4(pk[q*4], pk[q*4+1], pk[q*4+2], pk[q*4+3]);
}

// ---------------- K2: k_z — iZ[j] via bf16 logit mma ---------------------------
#define LPAD 40
#define KZ_SMEM (128*LPAD*2*3 + 512)

__global__ void __launch_bounds__(256, 2) k_z()
{
    extern __shared__ char smz[];
    __nv_bfloat16* Bs  = (__nv_bfloat16*)smz;
    __nv_bfloat16* As0 = Bs + 128*LPAD;
    float* Zsm = (float*)(smz + 128*LPAD*2*3);

    const int b  = blockIdx.y;
    const int j0 = blockIdx.x * 128;
    const __nv_bfloat16* Ah = g_Ah[b];
    const __nv_bfloat16* Bh = g_Bh[b];
    const int tid  = threadIdx.x;
    const int lane = tid & 31;
    const int warp = tid >> 5;
    const int wm   = warp & 1;
    const int wn   = warp >> 1;
    const int lr   = lane >> 2;
    const int lc   = lane & 3;

    const int a_lr = ((lane>>3)&1)*8 + (lane&7);
    const int a_cb = ((lane>>4)&1)*16;
    const int b4_row = ((lane>>4)&1)*8 + (lane&7);
    const int b4_kh  = ((lane>>3)&1)*16;

    #pragma unroll
    for (int r = 0; r < 2; r++) {
        int idx = tid + 256*r;
        int row = idx >> 2, q = idx & 3;
        *(uint4*)(Bs + row*LPAD + q*8) = *(const uint4*)(Bh + (size_t)(j0+row)*MIDD + q*8);
    }
    if (tid < 128) Zsm[tid] = 0.f;

    #define STAGE_AZ(dst, ib) do {                                              \
        _Pragma("unroll")                                                       \
        for (int r = 0; r < 2; r++) {                                           \
            int idx = tid + 256*r;                                              \
            int row = idx >> 2, q = idx & 3;                                    \
            *(uint4*)((dst) + row*LPAD + q*8) =                                 \
                *(const uint4*)(Ah + (size_t)((ib)+row)*MIDD + q*8);            \
        }                                                                       \
    } while (0)

    STAGE_AZ(As0, 0);
    __syncthreads();

    float z0[4], z1[4];
    #pragma unroll
    for (int nf = 0; nf < 4; nf++) { z0[nf] = 0.f; z1[nf] = 0.f; }

    for (int ic = 0; ic < 32; ic++) {
        const int s = ic & 1;
        const uint32_t asb = smem_u32(As0 + s*128*LPAD);
        const uint32_t bsb = smem_u32(Bs);
        if (ic + 1 < 32) STAGE_AZ(As0 + (s^1)*128*LPAD, (ic+1)*128);

        float acc[4][4][4];
        #pragma unroll
        for (int mf = 0; mf < 4; mf++)
            #pragma unroll
            for (int nf = 0; nf < 4; nf++)
                #pragma unroll
                for (int q = 0; q < 4; q++) acc[mf][nf][q] = 0.f;

        #pragma unroll
        for (int ks = 0; ks < 2; ks++) {
            const int jbB = ks * 32;
            uint32_t afr[4][4], bfr[4][2];
            #pragma unroll
            for (int mf = 0; mf < 4; mf++)
                ldsm_x4(afr[mf][0], afr[mf][1], afr[mf][2], afr[mf][3],
                        asb + (wm*64 + mf*16 + a_lr)*(LPAD*2) + jbB + a_cb);
            #pragma unroll
            for (int nfb = 0; nfb < 4; nfb += 2)
                ldsm_x4(bfr[nfb][0], bfr[nfb][1], bfr[nfb+1][0], bfr[nfb+1][1],
                        bsb + (wn*32 + nfb*8 + b4_row)*(LPAD*2) + jbB + b4_kh);
            #pragma unroll
            for (int mf = 0; mf < 4; mf++)
                #pragma unroll
                for (int nf = 0; nf < 4; nf++)
                    mma_bf16(acc[mf][nf], afr[mf], bfr[nf]);
        }

        #pragma unroll
        for (int mf = 0; mf < 4; mf++)
            #pragma unroll
            for (int nf = 0; nf < 4; nf++) {
                z0[nf] += __expf(acc[mf][nf][0] - MSHIFT) + __expf(acc[mf][nf][2] - MSHIFT);
                z1[nf] += __expf(acc[mf][nf][1] - MSHIFT) + __expf(acc[mf][nf][3] - MSHIFT);
            }
        __syncthreads();
    }

    #pragma unroll
    for (int nf = 0; nf < 4; nf++) {
        float s0 = z0[nf], s1 = z1[nf];
        #pragma unroll
        for (int msk = 4; msk <= 16; msk <<= 1) {
            s0 += __shfl_xor_sync(0xFFFFFFFF, s0, msk);
            s1 += __shfl_xor_sync(0xFFFFFFFF, s1, msk);
        }
        if (lr == 0) {
            atomicAdd(&Zsm[wn*32 + nf*8 + 2*lc],     s0);
            atomicAdd(&Zsm[wn*32 + nf*8 + 2*lc + 1], s1);
        }
    }
    __syncthreads();
    if (tid < 128) g_iZ[b*NN + j0 + tid] = 1.f / Zsm[tid];
}

// ---------------- K3: bf16 mma conv: CsH[k][n] = Wc X + bc (raw) ----------------
#define KCPAD 40
__global__ void __launch_bounds__(256, 2) k_c_mma(
    const float* __restrict__ x, const float* __restrict__ wc,
    const float* __restrict__ bc)
{
    __shared__ __nv_bfloat16 Wt[2][128*KCPAD];
    __shared__ __nv_bfloat16 Xt[2][128*KCPAD];

    const int tid  = threadIdx.x;
    const int lane = tid & 31;
    const int warp = tid >> 5;
    const int wm   = warp & 1;
    const int wn   = warp >> 1;
    const int lr   = lane >> 2;
    const int lc   = lane & 3;
    const int n0   = blockIdx.x * 128;
    const int b    = blockIdx.y;
    const int kz   = blockIdx.z;
    const float* xb = x + (size_t)b*CC*NN;

    const int a_lr = ((lane>>3)&1)*8 + (lane&7);
    const int a_cb = ((lane>>4)&1)*16;
    const int b4_row = ((lane>>4)&1)*8 + (lane&7);
    const int b4_kh  = ((lane>>3)&1)*16;

    float acc[4][4][4];
    #pragma unroll
    for (int mf = 0; mf < 4; mf++)
        #pragma unroll
        for (int nf = 0; nf < 4; nf++)
            #pragma unroll
            for (int q = 0; q < 4; q++) acc[mf][nf][q] = 0.f;

    const int xt = tid & 127, xch = tid >> 7;

    #define STAGE_C(s, c0) do {                                                 \
        _Pragma("unroll")                                                       \
        for (int r = 0; r < 8; r++) {                                           \
            int idx = tid + 256*r;                                              \
            int k = idx >> 4, cp = idx & 15;                                    \
            float2 w2 = *(const float2*)(wc + (kz*128 + k)*CC + (c0) + cp*2);   \
            *(uint32_t*)&Wt[s][k*KCPAD + cp*2] = pk_bf2(w2.x, w2.y);            \
        }                                                                       \
        _Pragma("unroll")                                                       \
        for (int r = 0; r < 16; r++) {                                          \
            int c = xch*16 + r;                                                 \
            Xt[s][xt*KCPAD + c] =                                               \
                __float2bfloat16(xb[(size_t)((c0) + c)*NN + n0 + xt]);          \
        }                                                                       \
    } while (0)

    STAGE_C(0, 0);
    __syncthreads();

    for (int ch = 0; ch < 8; ch++) {
        const int s = ch & 1;
        if (ch + 1 < 8) STAGE_C(s^1, (ch+1)*32);

        const uint32_t wtb = smem_u32(&Wt[s][0]);
        const uint32_t xtb = smem_u32(&Xt[s][0]);
        #pragma unroll
        for (int ks = 0; ks < 2; ks++) {
            const int jbB = ks * 32;
            uint32_t afr[4][4], bfr[4][2];
            #pragma unroll
            for (int mf = 0; mf < 4; mf++)
                ldsm_x4(afr[mf][0], afr[mf][1], afr[mf][2], afr[mf][3],
                        wtb + (wm*64 + mf*16 + a_lr)*(KCPAD*2) + jbB + a_cb);
            #pragma unroll
            for (int nfb = 0; nfb < 4; nfb += 2)
                ldsm_x4(bfr[nfb][0], bfr[nfb][1], bfr[nfb+1][0], bfr[nfb+1][1],
                        xtb + (wn*32 + nfb*8 + b4_row)*(KCPAD*2) + jbB + b4_kh);
            #pragma unroll
            for (int mf = 0; mf < 4; mf++)
                #pragma unroll
                for (int nf = 0; nf < 4; nf++)
                    mma_bf16(acc[mf][nf], afr[mf], bfr[nf]);
        }
        __syncthreads();
    }

    __nv_bfloat16* Cb = g_CsH[b];
    #pragma unroll
    for (int mf = 0; mf < 4; mf++) {
        int krow = kz*128 + wm*64 + mf*16 + lr;
        float bc0 = __ldg(bc + krow), bc8 = __ldg(bc + krow + 8);
        #pragma unroll
        for (int nf = 0; nf < 4; nf++) {
            int col = n0 + wn*32 + nf*8 + 2*lc;
            *(uint32_t*)(Cb + (size_t)krow*NN + col) =
                pk_bf2(acc[mf][nf][0] + bc0, acc[mf][nf][1] + bc0);
            *(uint32_t*)(Cb + (size_t)(krow+8)*NN + col) =
                pk_bf2(acc[mf][nf][2] + bc8, acc[mf][nf][3] + bc8);
        }
    }
}

// ---------------- K4: fused attention-out; bf16 logits; M=64, 2 CTAs/SM ---------
// iZ read DIRECTLY from gmem in EXP_STORE (race-free; L2-resident).
#define EROW2 144
#define OF_ET 8192
#define ETB   9216
#define OF_CS 26624
#define CSB   36864
#define KOF_SMEM 100352

__global__ void __launch_bounds__(256, 2) k_out_f()
{
    extern __shared__ char sm[];
    const uint32_t sb = smem_u32(sm);
    const int tid  = threadIdx.x;
    const int lane = tid & 31;
    const int warp = tid >> 5;
    const int wn   = warp;        // main: N eighth
    const int wi   = warp & 1;    // logit: i half
    const int wj   = warp >> 1;   // logit: j quarter
    const int lr   = lane >> 2;
    const int lc   = lane & 3;
    const int b    = blockIdx.y;
    const int i0   = blockIdx.x * 64;

    const __nv_bfloat16* Ah = g_Ah[b];
    const __nv_bfloat16* Bh = g_Bh[b];
    const __nv_bfloat16* Ch = g_CsH[b];
    const float* iZb = g_iZ + b*NN;

    const int a_lr = ((lane>>3)&1)*8 + (lane&7);
    const int a_cb = ((lane>>4)&1)*16;
    const int b4_row = ((lane>>4)&1)*8 + (lane&7);
    const int b4_kh  = ((lane>>3)&1)*16;

    #define ISSUE_CS(ch, s) do {                                                \
        uint32_t cb = sb + OF_CS + (s)*CSB;                                     \
        int _j = (ch)*64;                                                       \
        _Pragma("unroll")                                                       \
        for (int r = 0; r < 8; r++) {                                           \
            int id = tid + 256*r; int row = id >> 3, q = id & 7;                \
            CP16(cb + row*EROW2 + q*16,                                         \
                 (const char*)(Ch + (size_t)row*NN + _j) + q*16);               \
        }                                                                       \
        CP_COMMIT();                                                            \
    } while (0)

    // logit tile 64i x 64j: bf16 mma; A from smem (ldsm), B direct from gmem
    #define LOGIT_MMA(lacc, ch) do {                                            \
        const int _j = (ch)*64;                                                 \
        uint32_t breg[2][2][2];                                                 \
        _Pragma("unroll")                                                       \
        for (int ks = 0; ks < 2; ks++)                                          \
            _Pragma("unroll")                                                   \
            for (int nf = 0; nf < 2; nf++) {                                    \
                int jcol = _j + wj*16 + nf*8 + lr;                              \
                breg[ks][nf][0] = *(const uint32_t*)(Bh + (size_t)jcol*MIDD + ks*16 + 2*lc);     \
                breg[ks][nf][1] = *(const uint32_t*)(Bh + (size_t)jcol*MIDD + ks*16 + 2*lc + 8); \
            }                                                                   \
        _Pragma("unroll")                                                       \
        for (int mf = 0; mf < 2; mf++)                                          \
            _Pragma("unroll")                                                   \
            for (int nf = 0; nf < 2; nf++)                                      \
                _Pragma("unroll")                                               \
                for (int q = 0; q < 4; q++) lacc[mf][nf][q] = 0.f;              \
        _Pragma("unroll")                                                       \
        for (int ks = 0; ks < 2; ks++) {                                        \
            uint32_t afr[2][4];                                                 \
            _Pragma("unroll")                                                   \
            for (int mf = 0; mf < 2; mf++)                                      \
                ldsm_x4(afr[mf][0], afr[mf][1], afr[mf][2], afr[mf][3],         \
                        sb + (wi*32 + mf*16 + a_lr)*(LPAD*2) + ks*32 + a_cb);   \
            _Pragma("unroll")                                                   \
            for (int mf = 0; mf < 2; mf++)                                      \
                _Pragma("unroll")                                               \
                for (int nf = 0; nf < 2; nf++)                                  \
                    mma_bf16(lacc[mf][nf], afr[mf], breg[ks][nf]);              \
        }                                                                       \
    } while (0)

    // iZ read straight from gmem (L2) — no cp.async handoff, no race.
    #define EXP_STORE(lacc, ch, s) do {                                         \
        uint32_t* Et = (uint32_t*)(sm + OF_ET + (s)*ETB);                       \
        const float* izp = iZb + (ch)*64;                                       \
        _Pragma("unroll")                                                       \
        for (int nf = 0; nf < 2; nf++) {                                        \
            const int colu = wj*8 + nf*4 + lc;                                  \
            const float iz0 = __ldg(izp + colu*2), iz1 = __ldg(izp + colu*2 + 1);\
            _Pragma("unroll")                                                   \
            for (int mf = 0; mf < 2; mf++) {                                    \
                const int row = wi*32 + mf*16 + lr;                             \
                float e0 = __expf(lacc[mf][nf][0] - MSHIFT) * iz0;              \
                float e1 = __expf(lacc[mf][nf][1] - MSHIFT) * iz1;              \
                float e2 = __expf(lacc[mf][nf][2] - MSHIFT) * iz0;              \
                float e3 = __expf(lacc[mf][nf][3] - MSHIFT) * iz1;              \
                Et[row*36 + colu]     = pk_bf2(e0, e1);                         \
                Et[(row+8)*36 + colu] = pk_bf2(e2, e3);                         \
            }                                                                   \
        }                                                                       \
    } while (0)

    // ---- prologue: stage AsH [64 i][32 m] bf16 (pure copy) ----
    {
        __nv_bfloat16* AsH = (__nv_bfloat16*)sm;
        int row = tid >> 2, q = tid & 3;
        *(uint4*)(AsH + row*LPAD + q*8) = *(const uint4*)(Ah + (size_t)(i0+row)*MIDD + q*8);
    }
    ISSUE_CS(0, 0);
    CP_WAIT(0);
    __syncthreads();

    {
        float lacc[2][2][4];
        LOGIT_MMA(lacc, 0);
        EXP_STORE(lacc, 0, 0);
    }
    __syncthreads();
    ISSUE_CS(1, 1);

    float acc[4][4][4];
    #pragma unroll
    for (int mf = 0; mf < 4; mf++)
        #pragma unroll
        for (int nf = 0; nf < 4; nf++)
            #pragma unroll
            for (int q = 0; q < 4; q++) acc[mf][nf][q] = 0.f;

    // ---- main loop ----
    for (int ch = 0; ch < 64; ch++) {
        const int s = ch & 1;

        const uint32_t etb = sb + OF_ET + s*ETB;
        const uint32_t csb = sb + OF_CS + s*CSB;
        #pragma unroll
        for (int ks = 0; ks < 4; ks++) {
            const int jbB = ks * 32;
            uint32_t afr[4][4], bfr[4][2];
            #pragma unroll
            for (int mf = 0; mf < 4; mf++)
                ldsm_x4(afr[mf][0], afr[mf][1], afr[mf][2], afr[mf][3],
                        etb + (mf*16 + a_lr)*EROW2 + jbB + a_cb);
            #pragma unroll
            for (int nfb = 0; nfb < 4; nfb += 2)
                ldsm_x4(bfr[nfb][0], bfr[nfb][1], bfr[nfb+1][0], bfr[nfb+1][1],
                        csb + (wn*32 + nfb*8 + b4_row)*EROW2 + jbB + b4_kh);
            #pragma unroll
            for (int mf = 0; mf < 4; mf++)
                #pragma unroll
                for (int nf = 0; nf < 4; nf++)
                    mma_bf16(acc[mf][nf], afr[mf], bfr[nf]);
        }

        if (ch + 1 < 64) {
            float lacc[2][2][4];
            LOGIT_MMA(lacc, ch+1);
            CP_WAIT(0);                 // own-thread Cs[s^1] copies done
            EXP_STORE(lacc, ch+1, s^1); // iZ from gmem: race-free
            __syncthreads();            // publish Cs[s^1] + Et[s^1] to all
            if (ch + 2 < 64) ISSUE_CS(ch+2, s);
        }
    }

    float* Ob = g_O[b];
    #pragma unroll
    for (int mf = 0; mf < 4; mf++) {
        int row0 = i0 + mf*16 + lr;
        #pragma unroll
        for (int nf = 0; nf < 4; nf++) {
            int col = wn*32 + nf*8 + 2*lc;
            *(float2*)(Ob + (size_t)row0*CC + col) =
                make_float2(acc[mf][nf][0], acc[mf][nf][1]);
            *(float2*)(Ob + (size_t)(row0+8)*CC + col) =
                make_float2(acc[mf][nf][2], acc[mf][nf][3]);
        }
    }
}

// ---------------- K5: tf32 mma conv, frag-order: out = Wo(beta*Y + X) + bo ------
#define APAD 36
#define KF_SMEM (16384*4)
__global__ void __launch_bounds__(256, 2) k_final_mma(
    const float* __restrict__ x, const float* __restrict__ wo,
    const float* __restrict__ bo, const float* __restrict__ beta,
    float* __restrict__ out)
{
    extern __shared__ float smf[];
    float* WtF0 = smf;
    float* VtF0 = smf + 8192;

    const int tid  = threadIdx.x;
    const int lane = tid & 31;
    const int warp = tid >> 5;
    const int wm   = warp & 1;
    const int wn   = warp >> 1;
    const int lr   = lane >> 2;
    const int lc   = lane & 3;
    const int n0   = blockIdx.x * 128;
    const int b    = blockIdx.y;
    const int kz   = blockIdx.z;
    const float bt = beta[0];
    const float* xb = x + (size_t)b*CC*NN;
    const float* Yb = g_O[b];

    float acc[4][4][4];
    #pragma unroll
    for (int mf = 0; mf < 4; mf++)
        #pragma unroll
        for (int nf = 0; nf < 4; nf++)
            #pragma unroll
            for (int q = 0; q < 4; q++) acc[mf][nf][q] = 0.f;

    const int xt = tid & 127, xch = tid >> 7;

    #define STAGE_F(s, c0) do {                                                 \
        float* WtF = WtF0 + (s)*4096;                                           \
        float* VtF = VtF0 + (s)*4096;                                           \
        _Pragma("unroll")                                                       \
        for (int r = 0; r < 16; r++) {                                          \
            int idx = tid + 256*r;                                              \
            int k = idx >> 5, c = idx & 31;                                     \
            int t = k >> 4, hi = (k >> 3) & 1, lr8 = k & 7;                     \
            int ks = c >> 3, c8 = c & 7, lcb = c8 & 3, q = hi + ((c8>>2) << 1); \
            WtF[((t*4 + ks)*32 + lr8*4 + lcb)*4 + q] =                          \
                to_tf32f(wo[(kz*128 + k)*CC + (c0) + c]);                       \
        }                                                                       \
        _Pragma("unroll")                                                       \
        for (int r = 0; r < 16; r++) {                                          \
            int c = xch*16 + r;                                                 \
            size_t off = (size_t)((c0) + c)*NN + n0 + xt;                       \
            int jt = xt >> 3, lr8 = xt & 7;                                     \
            int ks = c >> 3, lcb = c & 3, qb = (c >> 2) & 1;                    \
            VtF[((jt*4 + ks)*32 + lr8*4 + lcb)*2 + qb] =                        \
                to_tf32f(fmaf(bt, Yb[off], xb[off]));                           \
        }                                                                       \
    } while (0)

    STAGE_F(0, 0);
    __syncthreads();

    for (int ch = 0; ch < 8; ch++) {
        const int s = ch & 1;
        if (ch + 1 < 8) STAGE_F(s^1, (ch+1)*32);

        const float4* WtF = (const float4*)(WtF0 + s*4096);
        const float2* VtF = (const float2*)(VtF0 + s*4096);
        #pragma unroll
        for (int ks = 0; ks < 4; ks++) {
            uint32_t afr[4][4], bfr[4][2];
            #pragma unroll
            for (int mf = 0; mf < 4; mf++) {
                float4 av = WtF[((wm*4 + mf)*4 + ks)*32 + lane];
                afr[mf][0] = __float_as_uint(av.x); afr[mf][1] = __float_as_uint(av.y);
                afr[mf][2] = __float_as_uint(av.z); afr[mf][3] = __float_as_uint(av.w);
            }
            #pragma unroll
            for (int nf = 0; nf < 4; nf++) {
                float2 bv = VtF[((wn*4 + nf)*4 + ks)*32 + lane];
                bfr[nf][0] = __float_as_uint(bv.x); bfr[nf][1] = __float_as_uint(bv.y);
            }
            #pragma unroll
            for (int mf = 0; mf < 4; mf++)
                #pragma unroll
                for (int nf = 0; nf < 4; nf++)
                    mma_tf32(acc[mf][nf], afr[mf], bfr[nf]);
        }
        __syncthreads();
    }

    #pragma unroll
    for (int mf = 0; mf < 4; mf++) {
        int krow = kz*128 + wm*64 + mf*16 + lr;
        float b0 = __ldg(bo + krow), b8 = __ldg(bo + krow + 8);
        #pragma unroll
        for (int nf = 0; nf < 4; nf++) {
            int col = n0 + wn*32 + nf*8 + 2*lc;
            *(float2*)(out + ((size_t)b*CC + krow)*NN + col) =
                make_float2(acc[mf][nf][0] + b0, acc[mf][nf][1] + b0);
            *(float2*)(out + ((size_t)b*CC + krow + 8)*NN + col) =
                make_float2(acc[mf][nf][2] + b8, acc[mf][nf][3] + b8);
        }
    }
}

// ---------------- launch --------------------------------------------------------
extern "C" void kernel_launch(void* const* d_in, const int* in_sizes, int n_in,
                              void* d_out, int out_size)
{
    const float* x    = (const float*)d_in[0];
    const float* wa   = (const float*)d_in[1];
    const float* ba   = (const float*)d_in[2];
    const float* wb   = (const float*)d_in[3];
    const float* bb   = (const float*)d_in[4];
    const float* wc   = (const float*)d_in[5];
    const float* bc   = (const float*)d_in[6];
    const float* wo   = (const float*)d_in[7];
    const float* bo   = (const float*)d_in[8];
    const float* beta = (const float*)d_in[9];
    float* out = (float*)d_out;

    cudaFuncSetAttribute(k_z,         cudaFuncAttributeMaxDynamicSharedMemorySize, KZ_SMEM);
    cudaFuncSetAttribute(k_out_f,     cudaFuncAttributeMaxDynamicSharedMemorySize, KOF_SMEM);
    cudaFuncSetAttribute(k_final_mma, cudaFuncAttributeMaxDynamicSharedMemorySize, KF_SMEM);

    k_ab       <<<dim3(NN/256, BB, 2),  256>>>(x, wa, ba, wb, bb);
    k_z        <<<dim3(NN/128, BB),     256, KZ_SMEM>>>();
    k_c_mma    <<<dim3(NN/128, BB, 2),  256>>>(x, wc, bc);
    k_out_f    <<<dim3(NN/64, BB),      256, KOF_SMEM>>>();
    k_final_mma<<<dim3(NN/128, BB, 2),  256, KF_SMEM>>>(x, wo, bo, beta, out);
}